// round 15
// baseline (speedup 1.0000x reference)
#include <cuda_runtime.h>

#define BB   4
#define CC_  64
#define HH   96
#define WW   96
#define HW_  (HH*WW)
#define CHW_ (CC_*HW_)

// padded pair-interleaved planes: [c2][y+3][x+3], PH x PW float2
#define PPAD  3
#define PH    102
#define PW    104
#define PLANE (PH*PW)

typedef unsigned long long ull;

// ---------------- packed f32x2 helpers ----------------
__device__ __forceinline__ ull pack2(float x, float y) {
    ull r; asm("mov.b64 %0, {%1, %2};" : "=l"(r) : "f"(x), "f"(y)); return r;
}
__device__ __forceinline__ float2 unpack2(ull v) {
    float2 t; asm("mov.b64 {%0, %1}, %2;" : "=f"(t.x), "=f"(t.y) : "l"(v)); return t;
}
__device__ __forceinline__ ull lds64f(const float* p) {
    ull r;
    asm("ld.shared.b64 %0, [%1];" : "=l"(r)
        : "l"((ull)__cvta_generic_to_shared(p)));
    return r;
}
__device__ __forceinline__ void lds128f(const float* p, ull& a, ull& b) {
    asm("ld.shared.v2.u64 {%0, %1}, [%2];" : "=l"(a), "=l"(b)
        : "l"((ull)__cvta_generic_to_shared(p)));
}
__device__ __forceinline__ void fma2(ull& d, ull a, ull b) {
    asm("fma.rn.f32x2 %0, %1, %2, %0;" : "+l"(d) : "l"(a), "l"(b));
}

// ---------------- scratch (static device globals; no allocation) ----------------
__device__ float  g_smooth[BB*CHW_];
__device__ float  g_sup2  [BB*CHW_];
__device__ float2 g_kpad  [BB*32*PLANE];        // sup2, padded + pair-interleaved
__device__ float2 g_vpad  [3*BB*32*PLANE];      // v per level, padded + interleaved
__device__ float  g_agg   [3*BB*CHW_];

// shift table: sh in (-3,0,3) x sw in (-3,0,3) minus (0,0)
__constant__ int c_sh[8] = {-3,-3,-3, 0, 0, 3, 3, 3};
__constant__ int c_sw[8] = {-3, 0, 3,-3, 3,-3, 0, 3};

// ---------------- kernel 0: zero the 3-wide halo ring of every padded plane ----
__global__ __launch_bounds__(256) void pad_border_kernel(
    float2* __restrict__ kpad, float2* __restrict__ vpad)
{
    int plane = blockIdx.x;     // 0..127 kpad, 128..511 vpad
    float2* base = (plane < BB*32) ? (kpad + plane*PLANE)
                                   : (vpad + (plane - BB*32)*PLANE);
    int tid = threadIdx.x;
    float2 z = make_float2(0.f, 0.f);
    // full border rows: y in [0,3) U [99,102)
    for (int e = tid; e < 6*PW; e += 256) {
        int r = e / PW, c = e % PW;
        int y = (r < 3) ? r : 96 + r;
        base[y*PW + c] = z;
    }
    // border cols of interior rows: x in [0,3) U [99,104), y in [3,99)
    for (int e = tid; e < 96*8; e += 256) {
        int r = e >> 3, c = e & 7;
        int x = (c < 3) ? c : 96 + c;
        base[(3 + r)*PW + x] = z;
    }
}

// ---------------- kernel 1: shift + grouped 3x3 conv (smooth) ----------------
__global__ __launch_bounds__(256) void smooth_kernel(
    const float* __restrict__ sup, const float* __restrict__ w,
    const float* __restrict__ bias, float* __restrict__ out)
{
    __shared__ float s_in[8*18*18];
    __shared__ float s_w [8*8*9];

    int bz = blockIdx.z;
    int g  = bz & 7;
    int b  = bz >> 3;
    int x0 = blockIdx.x * 16, y0 = blockIdx.y * 16;
    int sh = c_sh[g], sw = c_sw[g];
    int tid = threadIdx.x;

    for (int e = tid; e < 8*324; e += 256) {
        int ci = e / 324, rem = e % 324;
        int rr = rem / 18, cc = rem % 18;
        int sy = y0 - 1 + rr;
        int sx = x0 - 1 + cc;
        int gy = sy - sh;
        int gx = sx - sw;
        float v = 0.f;
        if (sy >= 0 && sy < HH && sx >= 0 && sx < WW &&
            gy >= 0 && gy < HH && gx >= 0 && gx < WW)
            v = sup[b*CHW_ + (g*8 + ci)*HW_ + gy*WW + gx];
        s_in[e] = v;
    }
    for (int e = tid; e < 576; e += 256) s_w[e] = w[g*8*72 + e];
    __syncthreads();

    int ty = tid >> 4, tx = tid & 15;
    float acc[8];
    #pragma unroll
    for (int j = 0; j < 8; j++) acc[j] = 0.f;

    #pragma unroll 1
    for (int ci = 0; ci < 8; ci++) {
        const float* base = s_in + ci*324 + ty*18 + tx;
        #pragma unroll
        for (int t = 0; t < 9; t++) {
            int dy = t / 3, dx = t % 3;
            float v = base[dy*18 + dx];
            #pragma unroll
            for (int co = 0; co < 8; co++)
                acc[co] = fmaf(s_w[co*72 + ci*9 + t], v, acc[co]);
        }
    }
    int y = y0 + ty, x = x0 + tx;
    #pragma unroll
    for (int co = 0; co < 8; co++)
        out[b*CHW_ + (g*8 + co)*HW_ + y*WW + x] = acc[co] + bias[g*8 + co];
}

// ---------------- kernel 2a: pointwise conv 1x1 CIN=128; writes sup2 + kpad ----
__global__ __launch_bounds__(256) void pw128_kernel(
    const float* __restrict__ inA, const float* __restrict__ inB,
    const float* __restrict__ wgt, const float* __restrict__ bias,
    float* __restrict__ out, float2* __restrict__ kpad)
{
    __shared__ float s_in[16*256];
    __shared__ float s_w [64*16];

    int b  = blockIdx.y;
    int p0 = blockIdx.x * 256;
    int tid = threadIdx.x;
    int pl = tid & 63;
    int cg = tid >> 6;

    float acc[4][16];
    #pragma unroll
    for (int k = 0; k < 4; k++)
        #pragma unroll
        for (int j = 0; j < 16; j++) acc[k][j] = 0.f;

    for (int c0 = 0; c0 < 128; c0 += 16) {
        #pragma unroll
        for (int i = 0; i < 16; i++) {
            int e  = tid + i*256;
            int ci = c0 + (e >> 8);
            int px = e & 255;
            const float* src = (ci < 64) ? (inA + b*CHW_ + ci*HW_)
                                         : (inB + b*CHW_ + (ci - 64)*HW_);
            s_in[e] = src[p0 + px];
        }
        #pragma unroll
        for (int i = 0; i < 4; i++) {
            int e = tid + i*256;
            int co = e >> 4, ci = e & 15;
            s_w[e] = wgt[co*128 + c0 + ci];
        }
        __syncthreads();

        #pragma unroll 4
        for (int ci = 0; ci < 16; ci++) {
            float v0 = s_in[ci*256 + pl];
            float v1 = s_in[ci*256 + pl + 64];
            float v2 = s_in[ci*256 + pl + 128];
            float v3 = s_in[ci*256 + pl + 192];
            #pragma unroll
            for (int j = 0; j < 16; j++) {
                float wv = s_w[(cg*16 + j)*16 + ci];
                acc[0][j] = fmaf(wv, v0, acc[0][j]);
                acc[1][j] = fmaf(wv, v1, acc[1][j]);
                acc[2][j] = fmaf(wv, v2, acc[2][j]);
                acc[3][j] = fmaf(wv, v3, acc[3][j]);
            }
        }
        __syncthreads();
    }

    #pragma unroll
    for (int j = 0; j < 16; j += 2) {
        int co = cg*16 + j;
        int c2 = co >> 1;
        float b0v = bias[co], b1v = bias[co + 1];
        float2* kp = kpad + (b*32 + c2)*PLANE;
        #pragma unroll
        for (int k = 0; k < 4; k++) {
            int px = p0 + pl + 64*k;
            float v0 = acc[k][j]     + b0v;
            float v1 = acc[k][j + 1] + b1v;
            out[b*CHW_ + co*HW_ + px]       = v0;
            out[b*CHW_ + (co + 1)*HW_ + px] = v1;
            int y = px / WW, x = px - y*WW;
            kp[(y + PPAD)*PW + (x + PPAD)] = make_float2(v0, v1);
        }
    }
}

// ---------------- kernel 2b: three 1x1 convs (64->64); writes vpad only --------
__global__ __launch_bounds__(256) void pw64x3_kernel(
    const float* __restrict__ inA,
    const float* __restrict__ w0, const float* __restrict__ b0,
    const float* __restrict__ w1, const float* __restrict__ b1,
    const float* __restrict__ w2, const float* __restrict__ b2,
    float2* __restrict__ vpad)
{
    __shared__ float s_in[16*256];
    __shared__ float s_w [64*16];

    int lvl = blockIdx.y >> 2;
    int b   = blockIdx.y & 3;
    const float* wgt  = (lvl == 0) ? w0 : (lvl == 1) ? w1 : w2;
    const float* bias = (lvl == 0) ? b0 : (lvl == 1) ? b1 : b2;
    float2* vb_ = vpad + (lvl*BB + b)*32*PLANE;

    int p0 = blockIdx.x * 256;
    int tid = threadIdx.x;
    int pl = tid & 63;
    int cg = tid >> 6;

    float acc[4][16];
    #pragma unroll
    for (int k = 0; k < 4; k++)
        #pragma unroll
        for (int j = 0; j < 16; j++) acc[k][j] = 0.f;

    for (int c0 = 0; c0 < 64; c0 += 16) {
        #pragma unroll
        for (int i = 0; i < 16; i++) {
            int e  = tid + i*256;
            int ci = c0 + (e >> 8);
            int px = e & 255;
            s_in[e] = inA[b*CHW_ + ci*HW_ + p0 + px];
        }
        #pragma unroll
        for (int i = 0; i < 4; i++) {
            int e = tid + i*256;
            int co = e >> 4, ci = e & 15;
            s_w[e] = wgt[co*64 + c0 + ci];
        }
        __syncthreads();

        #pragma unroll 4
        for (int ci = 0; ci < 16; ci++) {
            float v0 = s_in[ci*256 + pl];
            float v1 = s_in[ci*256 + pl + 64];
            float v2 = s_in[ci*256 + pl + 128];
            float v3 = s_in[ci*256 + pl + 192];
            #pragma unroll
            for (int j = 0; j < 16; j++) {
                float wv = s_w[(cg*16 + j)*16 + ci];
                acc[0][j] = fmaf(wv, v0, acc[0][j]);
                acc[1][j] = fmaf(wv, v1, acc[1][j]);
                acc[2][j] = fmaf(wv, v2, acc[2][j]);
                acc[3][j] = fmaf(wv, v3, acc[3][j]);
            }
        }
        __syncthreads();
    }

    #pragma unroll
    for (int j = 0; j < 16; j += 2) {
        int co = cg*16 + j;
        int c2 = co >> 1;
        float b0v = bias[co], b1v = bias[co + 1];
        float2* vp = vb_ + c2*PLANE;
        #pragma unroll
        for (int k = 0; k < 4; k++) {
            int px = p0 + pl + 64*k;
            float v0 = acc[k][j]     + b0v;
            float v1 = acc[k][j + 1] + b1v;
            int y = px / WW, x = px - y*WW;
            vp[(y + PPAD)*PW + (x + PPAD)] = make_float2(v0, v1);
        }
    }
}

// ---------------- kernel 3: fused NATTEN, channel-split, padded tile loads -----
// thread (h, px): h = warp-half (channels h*32..h*32+31), px = pixel.
template<int KS>
__global__ __launch_bounds__(256) void natten_kernel(
    const float* __restrict__ q, const float2* __restrict__ kpad,
    const float2* __restrict__ vpad, const float* __restrict__ rpb,
    float* __restrict__ out)
{
    constexpr int R    = KS/2;
    constexpr int YR   = 8  + 2*R;
    constexpr int XR   = 16 + 2*R;
    constexpr int TILE = YR*XR;
    constexpr int KSQ  = KS*KS;
    constexpr int RPB  = 2*KS - 1;

    extern __shared__ float sm[];
    float* s_k    = sm;                   // 64*TILE floats (32 c2-pairs)
    float* s_v    = s_k + 64*TILE;
    float* s_rpb  = s_v + 64*TILE;
    float* s_part = s_rpb + RPB*RPB;      // [2][128][KSQ]

    int b  = blockIdx.z;
    int x0 = blockIdx.x * 16;
    int y0 = blockIdx.y * 8;
    int tid = threadIdx.x;
    int h   = tid >> 7;
    int px  = tid & 127;

    // tile load from padded interleaved planes: coalesced LDG.64, no branches
    const float2* kb2 = kpad + (b*32)*PLANE;
    const float2* vb2 = vpad + (b*32)*PLANE;
    int base_off = (y0 - R + PPAD)*PW + (x0 - R + PPAD);
    for (int e = tid; e < 32*TILE; e += 256) {
        int c2  = e / TILE;
        int rem = e % TILE;
        int yy  = rem / XR, xx = rem % XR;
        int off = c2*PLANE + base_off + yy*PW + xx;
        float2 kv = kb2[off];
        float2 vv = vb2[off];
        *(float2*)&s_k[2*e] = kv;
        *(float2*)&s_v[2*e] = vv;
    }
    for (int e = tid; e < RPB*RPB; e += 256) s_rpb[e] = rpb[e];
    __syncthreads();

    int ty = px >> 4, tx = px & 15;
    int y = y0 + ty, x = x0 + tx;

    // q registers for this half's 16 channel-pairs
    ull q2[16];
    #pragma unroll
    for (int i = 0; i < 16; i++) {
        int c2 = h*16 + i;
        const float* qp = q + b*CHW_ + (2*c2)*HW_ + y*WW + x;
        q2[i] = pack2(qp[0], qp[HW_]);
    }

    int ni = min(max(y - R, 0), HH - KS);
    int nj = min(max(x - R, 0), WW - KS);
    int yy0 = ni - (y0 - R);
    int xx0 = nj - (x0 - R);
    int pi  = KS - 1 + ni - y;
    int pj  = KS - 1 + nj - x;

    // QK partial dots over this half's 32 channels
    #pragma unroll 1
    for (int p = 0; p < KS; p++) {
        #pragma unroll
        for (int qq = 0; qq < KS; qq++) {
            const float* kp = s_k + 2*((h*16)*TILE + (yy0 + p)*XR + xx0 + qq);
            ull s0 = 0ull, s1 = 0ull, s2 = 0ull, s3 = 0ull;
            #pragma unroll
            for (int i = 0; i < 16; i += 4) {
                fma2(s0, q2[i],     lds64f(kp + 2*(i    )*TILE));
                fma2(s1, q2[i + 1], lds64f(kp + 2*(i + 1)*TILE));
                fma2(s2, q2[i + 2], lds64f(kp + 2*(i + 2)*TILE));
                fma2(s3, q2[i + 3], lds64f(kp + 2*(i + 3)*TILE));
            }
            float2 ua = unpack2(s0), ub = unpack2(s1);
            float2 uc = unpack2(s2), ud = unpack2(s3);
            s_part[h*128*KSQ + px*KSQ + p*KS + qq] =
                ((ua.x + ua.y) + (ub.x + ub.y)) + ((uc.x + uc.y) + (ud.x + ud.y));
        }
    }
    __syncthreads();

    // every thread: combine partials + rpb, softmax in registers
    float ar[KSQ];
    float mx = -1e30f;
    #pragma unroll
    for (int t = 0; t < KSQ; t++) {
        int p = t / KS, qq = t % KS;
        float dot = s_part[px*KSQ + t] + s_part[128*KSQ + px*KSQ + t]
                  + s_rpb[(pi + p)*RPB + pj + qq];
        ar[t] = dot;
        mx = fmaxf(mx, dot);
    }
    float ssum = 0.f;
    #pragma unroll
    for (int t = 0; t < KSQ; t++) {
        float e = __expf(ar[t] - mx);
        ar[t] = e;
        ssum += e;
    }
    float inv = 1.0f / ssum;

    // AV over this half's 16 channel-pairs
    ull accv[16];
    #pragma unroll
    for (int i = 0; i < 16; i++) accv[i] = 0ull;
    #pragma unroll 1
    for (int p = 0; p < KS; p++) {
        #pragma unroll
        for (int qq = 0; qq < KS; qq++) {
            float av = ar[p*KS + qq] * inv;
            ull a2 = pack2(av, av);
            const float* vp = s_v + 2*((h*16)*TILE + (yy0 + p)*XR + xx0 + qq);
            #pragma unroll
            for (int i = 0; i < 16; i++)
                fma2(accv[i], a2, lds64f(vp + 2*i*TILE));
        }
    }
    float* ob = out + b*CHW_ + y*WW + x;
    #pragma unroll
    for (int i = 0; i < 16; i++) {
        float2 rv = unpack2(accv[i]);
        int c = 2*(h*16 + i);
        ob[c*HW_]       = rv.x;
        ob[(c + 1)*HW_] = rv.y;
    }
}

// ---------------- kernel 4: fusion 3x3 conv (256 -> 64) + ReLU, f32x2, 512 thr ----
__global__ __launch_bounds__(512) void fusion_kernel(
    const float* __restrict__ sup, const float* __restrict__ agg,
    const float* __restrict__ fw,  const float* __restrict__ fb,
    float* __restrict__ out)
{
    extern __shared__ float smf[];
    float* s_in = smf;            // 16 ci x 18 rows x stride 20 = 5760
    float* s_w2 = smf + 5760;     // 64 co x 16 ci x 10 x 2 = 20480

    int b  = blockIdx.z;
    int x0 = blockIdx.x * 16, y0 = blockIdx.y * 16;
    int tid = threadIdx.x;
    int pl  = tid & 63;
    int cg  = tid >> 6;           // 8 co-groups of 8
    int r   = pl >> 2;            // output row 0..15
    int qd  = pl & 3;             // x-quad

    ull acc[2][8];
    #pragma unroll
    for (int kk = 0; kk < 2; kk++)
        #pragma unroll
        for (int j = 0; j < 8; j++) acc[kk][j] = 0ull;

    #pragma unroll 1
    for (int src = 0; src < 4; src++) {
        const float* ip = (src == 0) ? (sup + b*CHW_)
                                     : (agg + (src - 1)*(BB*CHW_) + b*CHW_);
        #pragma unroll 1
        for (int c0 = 0; c0 < 64; c0 += 16) {
            for (int e = tid; e < 16*324; e += 512) {
                int ci  = e / 324, rem = e % 324;
                int rr  = rem / 18, cc = rem % 18;
                int gy  = y0 - 1 + rr, gx = x0 - 1 + cc;
                float vv = 0.f;
                if (gy >= 0 && gy < HH && gx >= 0 && gx < WW)
                    vv = ip[(c0 + ci)*HW_ + gy*WW + gx];
                s_in[ci*360 + rr*20 + cc] = vv;
            }
            int cinb = src*64 + c0;
            for (int e = tid; e < 64*144; e += 512) {
                int co  = e / 144, rem = e % 144;
                int ci  = rem / 9, t = rem - ci*9;
                float wv = fw[co*2304 + cinb*9 + rem];
                int pos = 2*((co*16 + ci)*10 + t);
                s_w2[pos] = wv; s_w2[pos + 1] = wv;
            }
            __syncthreads();

            #pragma unroll 1
            for (int ci = 0; ci < 16; ci++) {
                const float* row = s_in + ci*360 + r*20 + qd*4;
                ull A[9], Bv[9];
                #pragma unroll
                for (int dy = 0; dy < 3; dy++) {
                    float2 P0 = *(const float2*)(row + dy*20 + 0);
                    float2 P1 = *(const float2*)(row + dy*20 + 2);
                    float2 P2 = *(const float2*)(row + dy*20 + 4);
                    A [dy*3 + 0] = pack2(P0.x, P0.y); Bv[dy*3 + 0] = pack2(P1.x, P1.y);
                    A [dy*3 + 1] = pack2(P0.y, P1.x); Bv[dy*3 + 1] = pack2(P1.y, P2.x);
                    A [dy*3 + 2] = pack2(P1.x, P1.y); Bv[dy*3 + 2] = pack2(P2.x, P2.y);
                }
                #pragma unroll
                for (int j = 0; j < 8; j++) {
                    const float* wp = s_w2 + 2*(((cg*8 + j)*16 + ci)*10);
                    ull wt[9];
                    lds128f(wp + 0,  wt[0], wt[1]);
                    lds128f(wp + 4,  wt[2], wt[3]);
                    lds128f(wp + 8,  wt[4], wt[5]);
                    lds128f(wp + 12, wt[6], wt[7]);
                    wt[8] = lds64f(wp + 16);
                    #pragma unroll
                    for (int t = 0; t < 9; t++) {
                        fma2(acc[0][j], wt[t], A[t]);
                        fma2(acc[1][j], wt[t], Bv[t]);
                    }
                }
            }
            __syncthreads();
        }
    }

    int y = y0 + r, xb = x0 + qd*4;
    #pragma unroll
    for (int j = 0; j < 8; j++) {
        int co = cg*8 + j;
        float bv = fb[co];
        float2 lo = unpack2(acc[0][j]);
        float2 hi = unpack2(acc[1][j]);
        float4 o;
        o.x = fmaxf(lo.x + bv, 0.f);
        o.y = fmaxf(lo.y + bv, 0.f);
        o.z = fmaxf(hi.x + bv, 0.f);
        o.w = fmaxf(hi.y + bv, 0.f);
        *(float4*)&out[b*CHW_ + co*HW_ + y*WW + xb] = o;
    }
}

// ---------------- launch ----------------
static int natten_smem_bytes(int ks) {
    int r  = ks/2;
    int yr = 8 + 2*r, xr = 16 + 2*r;
    return (2*64*yr*xr + (2*ks - 1)*(2*ks - 1) + 2*128*ks*ks) * 4;
}

extern "C" void kernel_launch(void* const* d_in, const int* in_sizes, int n_in,
                              void* d_out, int out_size)
{
    const float* sup = (const float*)d_in[0];
    const float* key = (const float*)d_in[1];
    const float* csw = (const float*)d_in[2];
    const float* csb = (const float*)d_in[3];
    const float* crw = (const float*)d_in[4];
    const float* crb = (const float*)d_in[5];

    const float *vw[3], *vb[3], *rpb[3];
    if (in_sizes[8] == 25) {
        // dict-insertion (interleaved): v_w0, v_b0, rpb0, v_w1, v_b1, rpb1, ...
        for (int l = 0; l < 3; l++) {
            vw[l]  = (const float*)d_in[6 + 3*l];
            vb[l]  = (const float*)d_in[7 + 3*l];
            rpb[l] = (const float*)d_in[8 + 3*l];
        }
    } else {
        // signature order
        for (int l = 0; l < 3; l++) {
            vw[l]  = (const float*)d_in[6 + 2*l];
            vb[l]  = (const float*)d_in[7 + 2*l];
            rpb[l] = (const float*)d_in[12 + l];
        }
    }
    const float* fw = (const float*)d_in[15];
    const float* fb = (const float*)d_in[16];
    float* out = (float*)d_out;

    float *smoothp, *sup2p, *aggp;
    float2 *kpadp, *vpadp;
    cudaGetSymbolAddress((void**)&smoothp, g_smooth);
    cudaGetSymbolAddress((void**)&sup2p,   g_sup2);
    cudaGetSymbolAddress((void**)&kpadp,   g_kpad);
    cudaGetSymbolAddress((void**)&vpadp,   g_vpad);
    cudaGetSymbolAddress((void**)&aggp,    g_agg);

    cudaFuncSetAttribute(natten_kernel<3>, cudaFuncAttributeMaxDynamicSharedMemorySize, natten_smem_bytes(3));
    cudaFuncSetAttribute(natten_kernel<5>, cudaFuncAttributeMaxDynamicSharedMemorySize, natten_smem_bytes(5));
    cudaFuncSetAttribute(natten_kernel<7>, cudaFuncAttributeMaxDynamicSharedMemorySize, natten_smem_bytes(7));
    cudaFuncSetAttribute(fusion_kernel,    cudaFuncAttributeMaxDynamicSharedMemorySize, (5760 + 20480)*4);

    // 0. zero padded-plane borders (independent of everything upstream)
    pad_border_kernel<<<512, 256>>>(kpadp, vpadp);

    // 1. spatial shift + grouped smooth conv
    smooth_kernel<<<dim3(6, 6, BB*8), 256>>>(sup, csw, csb, smoothp);

    // 2. sup2 = 1x1 reduce; also writes padded interleaved kpad
    pw128_kernel<<<dim3(HW_/256, BB), 256>>>(sup, smoothp, crw, crb, sup2p, kpadp);

    // 3. all three v convs in one launch -> padded interleaved vpad
    pw64x3_kernel<<<dim3(HW_/256, BB*3), 256>>>(sup2p,
        vw[0], vb[0], vw[1], vb[1], vw[2], vb[2], vpadp);

    natten_kernel<3><<<dim3(6, 12, BB), 256, natten_smem_bytes(3)>>>(
        key, kpadp, vpadp + 0*(BB*32*PLANE), rpb[0], aggp + 0*(BB*CHW_));
    natten_kernel<5><<<dim3(6, 12, BB), 256, natten_smem_bytes(5)>>>(
        key, kpadp, vpadp + 1*(BB*32*PLANE), rpb[1], aggp + 1*(BB*CHW_));
    natten_kernel<7><<<dim3(6, 12, BB), 256, natten_smem_bytes(7)>>>(
        key, kpadp, vpadp + 2*(BB*32*PLANE), rpb[2], aggp + 2*(BB*CHW_));

    // 4. fusion 3x3 + ReLU (packed f32x2, 512 threads, LDS.128 weights)
    fusion_kernel<<<dim3(6, 6, BB), 512, (5760 + 20480)*4>>>(sup, aggp, fw, fb, out);
}

// round 16
// speedup vs baseline: 1.0098x; 1.0098x over previous
#include <cuda_runtime.h>

#define BB   4
#define CC_  64
#define HH   96
#define WW   96
#define HW_  (HH*WW)
#define CHW_ (CC_*HW_)

// padded pair-interleaved planes: [c2][y+3][x+3], PH x PW float2
#define PPAD  3
#define PH    102
#define PW    104
#define PLANE (PH*PW)

typedef unsigned long long ull;

// ---------------- packed f32x2 helpers ----------------
__device__ __forceinline__ ull pack2(float x, float y) {
    ull r; asm("mov.b64 %0, {%1, %2};" : "=l"(r) : "f"(x), "f"(y)); return r;
}
__device__ __forceinline__ float2 unpack2(ull v) {
    float2 t; asm("mov.b64 {%0, %1}, %2;" : "=f"(t.x), "=f"(t.y) : "l"(v)); return t;
}
__device__ __forceinline__ ull lds64f(const float* p) {
    ull r;
    asm("ld.shared.b64 %0, [%1];" : "=l"(r)
        : "l"((ull)__cvta_generic_to_shared(p)));
    return r;
}
__device__ __forceinline__ void lds128f(const float* p, ull& a, ull& b) {
    asm("ld.shared.v2.u64 {%0, %1}, [%2];" : "=l"(a), "=l"(b)
        : "l"((ull)__cvta_generic_to_shared(p)));
}
__device__ __forceinline__ void fma2(ull& d, ull a, ull b) {
    asm("fma.rn.f32x2 %0, %1, %2, %0;" : "+l"(d) : "l"(a), "l"(b));
}

// ---------------- scratch (static device globals; no allocation) ----------------
__device__ float  g_smooth[BB*CHW_];
__device__ float  g_sup2  [BB*CHW_];
__device__ float2 g_kpad  [BB*32*PLANE];
__device__ float2 g_vpad  [3*BB*32*PLANE];
__device__ float  g_agg   [3*BB*CHW_];

// shift table: sh in (-3,0,3) x sw in (-3,0,3) minus (0,0)
__constant__ int c_sh[8] = {-3,-3,-3, 0, 0, 3, 3, 3};
__constant__ int c_sw[8] = {-3, 0, 3,-3, 3,-3, 0, 3};

// ---------------- kernel 0: zero the 3-wide halo ring of every padded plane ----
__global__ __launch_bounds__(256) void pad_border_kernel(
    float2* __restrict__ kpad, float2* __restrict__ vpad)
{
    int plane = blockIdx.x;     // 0..127 kpad, 128..511 vpad
    float2* base = (plane < BB*32) ? (kpad + plane*PLANE)
                                   : (vpad + (plane - BB*32)*PLANE);
    int tid = threadIdx.x;
    float2 z = make_float2(0.f, 0.f);
    for (int e = tid; e < 6*PW; e += 256) {
        int r = e / PW, c = e % PW;
        int y = (r < 3) ? r : 96 + r;
        base[y*PW + c] = z;
    }
    for (int e = tid; e < 96*8; e += 256) {
        int r = e >> 3, c = e & 7;
        int x = (c < 3) ? c : 96 + c;
        base[(3 + r)*PW + x] = z;
    }
}

// ---------------- kernel 1: shift + grouped 3x3 conv (smooth) ----------------
__global__ __launch_bounds__(256) void smooth_kernel(
    const float* __restrict__ sup, const float* __restrict__ w,
    const float* __restrict__ bias, float* __restrict__ out)
{
    __shared__ float s_in[8*18*18];
    __shared__ float s_w [8*8*9];

    int bz = blockIdx.z;
    int g  = bz & 7;
    int b  = bz >> 3;
    int x0 = blockIdx.x * 16, y0 = blockIdx.y * 16;
    int sh = c_sh[g], sw = c_sw[g];
    int tid = threadIdx.x;

    for (int e = tid; e < 8*324; e += 256) {
        int ci = e / 324, rem = e % 324;
        int rr = rem / 18, cc = rem % 18;
        int sy = y0 - 1 + rr;
        int sx = x0 - 1 + cc;
        int gy = sy - sh;
        int gx = sx - sw;
        float v = 0.f;
        if (sy >= 0 && sy < HH && sx >= 0 && sx < WW &&
            gy >= 0 && gy < HH && gx >= 0 && gx < WW)
            v = sup[b*CHW_ + (g*8 + ci)*HW_ + gy*WW + gx];
        s_in[e] = v;
    }
    for (int e = tid; e < 576; e += 256) s_w[e] = w[g*8*72 + e];
    __syncthreads();

    int ty = tid >> 4, tx = tid & 15;
    float acc[8];
    #pragma unroll
    for (int j = 0; j < 8; j++) acc[j] = 0.f;

    #pragma unroll 1
    for (int ci = 0; ci < 8; ci++) {
        const float* base = s_in + ci*324 + ty*18 + tx;
        #pragma unroll
        for (int t = 0; t < 9; t++) {
            int dy = t / 3, dx = t % 3;
            float v = base[dy*18 + dx];
            #pragma unroll
            for (int co = 0; co < 8; co++)
                acc[co] = fmaf(s_w[co*72 + ci*9 + t], v, acc[co]);
        }
    }
    int y = y0 + ty, x = x0 + tx;
    #pragma unroll
    for (int co = 0; co < 8; co++)
        out[b*CHW_ + (g*8 + co)*HW_ + y*WW + x] = acc[co] + bias[g*8 + co];
}

// ---------------- kernel 2a: pw 1x1 CIN=128, f32x2 co-pairs; sup2 + kpad ------
__global__ __launch_bounds__(256) void pw128_kernel(
    const float* __restrict__ inA, const float* __restrict__ inB,
    const float* __restrict__ wgt, const float* __restrict__ bias,
    float* __restrict__ out, float2* __restrict__ kpad)
{
    __shared__ float s_in[16*256];
    __shared__ float s_w [16*64];      // [ci][co] -> co-pairs adjacent

    int b  = blockIdx.y;
    int p0 = blockIdx.x * 256;
    int tid = threadIdx.x;
    int pl = tid & 63;
    int cg = tid >> 6;

    ull acc2[4][8];
    #pragma unroll
    for (int k = 0; k < 4; k++)
        #pragma unroll
        for (int j = 0; j < 8; j++) acc2[k][j] = 0ull;

    for (int c0 = 0; c0 < 128; c0 += 16) {
        #pragma unroll
        for (int i = 0; i < 16; i++) {
            int e  = tid + i*256;
            int ci = c0 + (e >> 8);
            int px = e & 255;
            const float* src = (ci < 64) ? (inA + b*CHW_ + ci*HW_)
                                         : (inB + b*CHW_ + (ci - 64)*HW_);
            s_in[e] = src[p0 + px];
        }
        #pragma unroll
        for (int i = 0; i < 4; i++) {
            int e = tid + i*256;
            int ci = e >> 6, co = e & 63;
            s_w[e] = wgt[co*128 + c0 + ci];
        }
        __syncthreads();

        #pragma unroll 4
        for (int ci = 0; ci < 16; ci++) {
            float v0 = s_in[ci*256 + pl];
            float v1 = s_in[ci*256 + pl + 64];
            float v2 = s_in[ci*256 + pl + 128];
            float v3 = s_in[ci*256 + pl + 192];
            ull vv0 = pack2(v0, v0), vv1 = pack2(v1, v1);
            ull vv2 = pack2(v2, v2), vv3 = pack2(v3, v3);
            const float* wp = s_w + ci*64 + cg*16;
            #pragma unroll
            for (int j = 0; j < 8; j++) {
                ull w2 = lds64f(wp + 2*j);
                fma2(acc2[0][j], w2, vv0);
                fma2(acc2[1][j], w2, vv1);
                fma2(acc2[2][j], w2, vv2);
                fma2(acc2[3][j], w2, vv3);
            }
        }
        __syncthreads();
    }

    #pragma unroll
    for (int k = 0; k < 4; k++) {
        int px = p0 + pl + 64*k;
        int y = px / WW, x = px - y*WW;
        int ro = (y + PPAD)*PW + (x + PPAD);
        #pragma unroll
        for (int j = 0; j < 8; j++) {
            int co = cg*16 + 2*j;
            float2 bv = *(const float2*)&bias[co];
            float2 r = unpack2(acc2[k][j]);
            r.x += bv.x; r.y += bv.y;
            out[b*CHW_ + co*HW_ + px]       = r.x;
            out[b*CHW_ + (co + 1)*HW_ + px] = r.y;
            kpad[(b*32 + cg*8 + j)*PLANE + ro] = r;
        }
    }
}

// ---------------- kernel 2b: pw 1x1 64->64 (one level), f32x2; vpad only ------
__global__ __launch_bounds__(256) void pw64_kernel(
    const float* __restrict__ inA,
    const float* __restrict__ wgt, const float* __restrict__ bias,
    float2* __restrict__ vpadl)
{
    __shared__ float s_in[16*256];
    __shared__ float s_w [16*64];      // [ci][co]

    int b  = blockIdx.y;
    int p0 = blockIdx.x * 256;
    int tid = threadIdx.x;
    int pl = tid & 63;
    int cg = tid >> 6;

    ull acc2[4][8];
    #pragma unroll
    for (int k = 0; k < 4; k++)
        #pragma unroll
        for (int j = 0; j < 8; j++) acc2[k][j] = 0ull;

    for (int c0 = 0; c0 < 64; c0 += 16) {
        #pragma unroll
        for (int i = 0; i < 16; i++) {
            int e  = tid + i*256;
            int ci = c0 + (e >> 8);
            int px = e & 255;
            s_in[e] = inA[b*CHW_ + ci*HW_ + p0 + px];
        }
        #pragma unroll
        for (int i = 0; i < 4; i++) {
            int e = tid + i*256;
            int ci = e >> 6, co = e & 63;
            s_w[e] = wgt[co*64 + c0 + ci];
        }
        __syncthreads();

        #pragma unroll 4
        for (int ci = 0; ci < 16; ci++) {
            float v0 = s_in[ci*256 + pl];
            float v1 = s_in[ci*256 + pl + 64];
            float v2 = s_in[ci*256 + pl + 128];
            float v3 = s_in[ci*256 + pl + 192];
            ull vv0 = pack2(v0, v0), vv1 = pack2(v1, v1);
            ull vv2 = pack2(v2, v2), vv3 = pack2(v3, v3);
            const float* wp = s_w + ci*64 + cg*16;
            #pragma unroll
            for (int j = 0; j < 8; j++) {
                ull w2 = lds64f(wp + 2*j);
                fma2(acc2[0][j], w2, vv0);
                fma2(acc2[1][j], w2, vv1);
                fma2(acc2[2][j], w2, vv2);
                fma2(acc2[3][j], w2, vv3);
            }
        }
        __syncthreads();
    }

    float2* vb_ = vpadl + b*32*PLANE;
    #pragma unroll
    for (int k = 0; k < 4; k++) {
        int px = p0 + pl + 64*k;
        int y = px / WW, x = px - y*WW;
        int ro = (y + PPAD)*PW + (x + PPAD);
        #pragma unroll
        for (int j = 0; j < 8; j++) {
            int co = cg*16 + 2*j;
            float2 bv = *(const float2*)&bias[co];
            float2 r = unpack2(acc2[k][j]);
            r.x += bv.x; r.y += bv.y;
            vb_[(cg*8 + j)*PLANE + ro] = r;
        }
    }
}

// ---------------- kernel 3: fused NATTEN, channel-split, padded tile loads -----
template<int KS>
__global__ __launch_bounds__(256) void natten_kernel(
    const float* __restrict__ q, const float2* __restrict__ kpad,
    const float2* __restrict__ vpad, const float* __restrict__ rpb,
    float* __restrict__ out)
{
    constexpr int R    = KS/2;
    constexpr int YR   = 8  + 2*R;
    constexpr int XR   = 16 + 2*R;
    constexpr int TILE = YR*XR;
    constexpr int KSQ  = KS*KS;
    constexpr int RPB  = 2*KS - 1;

    extern __shared__ float sm[];
    float* s_k    = sm;
    float* s_v    = s_k + 64*TILE;
    float* s_rpb  = s_v + 64*TILE;
    float* s_part = s_rpb + RPB*RPB;      // [2][128][KSQ]

    int b  = blockIdx.z;
    int x0 = blockIdx.x * 16;
    int y0 = blockIdx.y * 8;
    int tid = threadIdx.x;
    int h   = tid >> 7;
    int px  = tid & 127;

    const float2* kb2 = kpad + (b*32)*PLANE;
    const float2* vb2 = vpad + (b*32)*PLANE;
    int base_off = (y0 - R + PPAD)*PW + (x0 - R + PPAD);
    for (int e = tid; e < 32*TILE; e += 256) {
        int c2  = e / TILE;
        int rem = e % TILE;
        int yy  = rem / XR, xx = rem % XR;
        int off = c2*PLANE + base_off + yy*PW + xx;
        float2 kv = kb2[off];
        float2 vv = vb2[off];
        *(float2*)&s_k[2*e] = kv;
        *(float2*)&s_v[2*e] = vv;
    }
    for (int e = tid; e < RPB*RPB; e += 256) s_rpb[e] = rpb[e];
    __syncthreads();

    int ty = px >> 4, tx = px & 15;
    int y = y0 + ty, x = x0 + tx;

    ull q2[16];
    #pragma unroll
    for (int i = 0; i < 16; i++) {
        int c2 = h*16 + i;
        const float* qp = q + b*CHW_ + (2*c2)*HW_ + y*WW + x;
        q2[i] = pack2(qp[0], qp[HW_]);
    }

    int ni = min(max(y - R, 0), HH - KS);
    int nj = min(max(x - R, 0), WW - KS);
    int yy0 = ni - (y0 - R);
    int xx0 = nj - (x0 - R);
    int pi  = KS - 1 + ni - y;
    int pj  = KS - 1 + nj - x;

    #pragma unroll 1
    for (int p = 0; p < KS; p++) {
        #pragma unroll
        for (int qq = 0; qq < KS; qq++) {
            const float* kp = s_k + 2*((h*16)*TILE + (yy0 + p)*XR + xx0 + qq);
            ull s0 = 0ull, s1 = 0ull, s2 = 0ull, s3 = 0ull;
            #pragma unroll
            for (int i = 0; i < 16; i += 4) {
                fma2(s0, q2[i],     lds64f(kp + 2*(i    )*TILE));
                fma2(s1, q2[i + 1], lds64f(kp + 2*(i + 1)*TILE));
                fma2(s2, q2[i + 2], lds64f(kp + 2*(i + 2)*TILE));
                fma2(s3, q2[i + 3], lds64f(kp + 2*(i + 3)*TILE));
            }
            float2 ua = unpack2(s0), ub = unpack2(s1);
            float2 uc = unpack2(s2), ud = unpack2(s3);
            s_part[h*128*KSQ + px*KSQ + p*KS + qq] =
                ((ua.x + ua.y) + (ub.x + ub.y)) + ((uc.x + uc.y) + (ud.x + ud.y));
        }
    }
    __syncthreads();

    float ar[KSQ];
    float mx = -1e30f;
    #pragma unroll
    for (int t = 0; t < KSQ; t++) {
        int p = t / KS, qq = t % KS;
        float dot = s_part[px*KSQ + t] + s_part[128*KSQ + px*KSQ + t]
                  + s_rpb[(pi + p)*RPB + pj + qq];
        ar[t] = dot;
        mx = fmaxf(mx, dot);
    }
    float ssum = 0.f;
    #pragma unroll
    for (int t = 0; t < KSQ; t++) {
        float e = __expf(ar[t] - mx);
        ar[t] = e;
        ssum += e;
    }
    float inv = 1.0f / ssum;

    ull accv[16];
    #pragma unroll
    for (int i = 0; i < 16; i++) accv[i] = 0ull;
    #pragma unroll 1
    for (int p = 0; p < KS; p++) {
        #pragma unroll
        for (int qq = 0; qq < KS; qq++) {
            float av = ar[p*KS + qq] * inv;
            ull a2 = pack2(av, av);
            const float* vp = s_v + 2*((h*16)*TILE + (yy0 + p)*XR + xx0 + qq);
            #pragma unroll
            for (int i = 0; i < 16; i++)
                fma2(accv[i], a2, lds64f(vp + 2*i*TILE));
        }
    }
    float* ob = out + b*CHW_ + y*WW + x;
    #pragma unroll
    for (int i = 0; i < 16; i++) {
        float2 rv = unpack2(accv[i]);
        int c = 2*(h*16 + i);
        ob[c*HW_]       = rv.x;
        ob[(c + 1)*HW_] = rv.y;
    }
}

// ---------------- kernel 4: fusion 3x3 conv (256 -> 64) + ReLU, f32x2, 512 thr ----
__global__ __launch_bounds__(512) void fusion_kernel(
    const float* __restrict__ sup, const float* __restrict__ agg,
    const float* __restrict__ fw,  const float* __restrict__ fb,
    float* __restrict__ out)
{
    extern __shared__ float smf[];
    float* s_in = smf;            // 16 ci x 18 rows x stride 20 = 5760
    float* s_w2 = smf + 5760;     // 64 co x 16 ci x 10 x 2 = 20480

    int b  = blockIdx.z;
    int x0 = blockIdx.x * 16, y0 = blockIdx.y * 16;
    int tid = threadIdx.x;
    int pl  = tid & 63;
    int cg  = tid >> 6;
    int r   = pl >> 2;
    int qd  = pl & 3;

    ull acc[2][8];
    #pragma unroll
    for (int kk = 0; kk < 2; kk++)
        #pragma unroll
        for (int j = 0; j < 8; j++) acc[kk][j] = 0ull;

    #pragma unroll 1
    for (int src = 0; src < 4; src++) {
        const float* ip = (src == 0) ? (sup + b*CHW_)
                                     : (agg + (src - 1)*(BB*CHW_) + b*CHW_);
        #pragma unroll 1
        for (int c0 = 0; c0 < 64; c0 += 16) {
            for (int e = tid; e < 16*324; e += 512) {
                int ci  = e / 324, rem = e % 324;
                int rr  = rem / 18, cc = rem % 18;
                int gy  = y0 - 1 + rr, gx = x0 - 1 + cc;
                float vv = 0.f;
                if (gy >= 0 && gy < HH && gx >= 0 && gx < WW)
                    vv = ip[(c0 + ci)*HW_ + gy*WW + gx];
                s_in[ci*360 + rr*20 + cc] = vv;
            }
            int cinb = src*64 + c0;
            for (int e = tid; e < 64*144; e += 512) {
                int co  = e / 144, rem = e % 144;
                int ci  = rem / 9, t = rem - ci*9;
                float wv = fw[co*2304 + cinb*9 + rem];
                int pos = 2*((co*16 + ci)*10 + t);
                s_w2[pos] = wv; s_w2[pos + 1] = wv;
            }
            __syncthreads();

            #pragma unroll 1
            for (int ci = 0; ci < 16; ci++) {
                const float* row = s_in + ci*360 + r*20 + qd*4;
                ull A[9], Bv[9];
                #pragma unroll
                for (int dy = 0; dy < 3; dy++) {
                    float2 P0 = *(const float2*)(row + dy*20 + 0);
                    float2 P1 = *(const float2*)(row + dy*20 + 2);
                    float2 P2 = *(const float2*)(row + dy*20 + 4);
                    A [dy*3 + 0] = pack2(P0.x, P0.y); Bv[dy*3 + 0] = pack2(P1.x, P1.y);
                    A [dy*3 + 1] = pack2(P0.y, P1.x); Bv[dy*3 + 1] = pack2(P1.y, P2.x);
                    A [dy*3 + 2] = pack2(P1.x, P1.y); Bv[dy*3 + 2] = pack2(P2.x, P2.y);
                }
                #pragma unroll
                for (int j = 0; j < 8; j++) {
                    const float* wp = s_w2 + 2*(((cg*8 + j)*16 + ci)*10);
                    ull wt[9];
                    lds128f(wp + 0,  wt[0], wt[1]);
                    lds128f(wp + 4,  wt[2], wt[3]);
                    lds128f(wp + 8,  wt[4], wt[5]);
                    lds128f(wp + 12, wt[6], wt[7]);
                    wt[8] = lds64f(wp + 16);
                    #pragma unroll
                    for (int t = 0; t < 9; t++) {
                        fma2(acc[0][j], wt[t], A[t]);
                        fma2(acc[1][j], wt[t], Bv[t]);
                    }
                }
            }
            __syncthreads();
        }
    }

    int y = y0 + r, xb = x0 + qd*4;
    #pragma unroll
    for (int j = 0; j < 8; j++) {
        int co = cg*8 + j;
        float bv = fb[co];
        float2 lo = unpack2(acc[0][j]);
        float2 hi = unpack2(acc[1][j]);
        float4 o;
        o.x = fmaxf(lo.x + bv, 0.f);
        o.y = fmaxf(lo.y + bv, 0.f);
        o.z = fmaxf(hi.x + bv, 0.f);
        o.w = fmaxf(hi.y + bv, 0.f);
        *(float4*)&out[b*CHW_ + co*HW_ + y*WW + xb] = o;
    }
}

// ---------------- launch ----------------
static int natten_smem_bytes(int ks) {
    int r  = ks/2;
    int yr = 8 + 2*r, xr = 16 + 2*r;
    return (2*64*yr*xr + (2*ks - 1)*(2*ks - 1) + 2*128*ks*ks) * 4;
}

extern "C" void kernel_launch(void* const* d_in, const int* in_sizes, int n_in,
                              void* d_out, int out_size)
{
    const float* sup = (const float*)d_in[0];
    const float* key = (const float*)d_in[1];
    const float* csw = (const float*)d_in[2];
    const float* csb = (const float*)d_in[3];
    const float* crw = (const float*)d_in[4];
    const float* crb = (const float*)d_in[5];

    const float *vw[3], *vb[3], *rpb[3];
    if (in_sizes[8] == 25) {
        for (int l = 0; l < 3; l++) {
            vw[l]  = (const float*)d_in[6 + 3*l];
            vb[l]  = (const float*)d_in[7 + 3*l];
            rpb[l] = (const float*)d_in[8 + 3*l];
        }
    } else {
        for (int l = 0; l < 3; l++) {
            vw[l]  = (const float*)d_in[6 + 2*l];
            vb[l]  = (const float*)d_in[7 + 2*l];
            rpb[l] = (const float*)d_in[12 + l];
        }
    }
    const float* fw = (const float*)d_in[15];
    const float* fb = (const float*)d_in[16];
    float* out = (float*)d_out;

    float *smoothp, *sup2p, *aggp;
    float2 *kpadp, *vpadp;
    cudaGetSymbolAddress((void**)&smoothp, g_smooth);
    cudaGetSymbolAddress((void**)&sup2p,   g_sup2);
    cudaGetSymbolAddress((void**)&kpadp,   g_kpad);
    cudaGetSymbolAddress((void**)&vpadp,   g_vpad);
    cudaGetSymbolAddress((void**)&aggp,    g_agg);

    cudaFuncSetAttribute(natten_kernel<3>, cudaFuncAttributeMaxDynamicSharedMemorySize, natten_smem_bytes(3));
    cudaFuncSetAttribute(natten_kernel<5>, cudaFuncAttributeMaxDynamicSharedMemorySize, natten_smem_bytes(5));
    cudaFuncSetAttribute(natten_kernel<7>, cudaFuncAttributeMaxDynamicSharedMemorySize, natten_smem_bytes(7));
    cudaFuncSetAttribute(fusion_kernel,    cudaFuncAttributeMaxDynamicSharedMemorySize, (5760 + 20480)*4);

    // one-time stream/event creation (first call is the uncaptured correctness
    // run; resources persist and are reused inside capture)
    static cudaStream_t t1 = 0, t2 = 0;
    static cudaEvent_t  evF = 0, ev1 = 0, ev2 = 0;
    static bool inited = false;
    static bool use_streams = false;
    if (!inited) {
        inited = true;
        bool ok = true;
        ok &= (cudaStreamCreateWithFlags(&t1, cudaStreamNonBlocking) == cudaSuccess);
        ok &= (cudaStreamCreateWithFlags(&t2, cudaStreamNonBlocking) == cudaSuccess);
        ok &= (cudaEventCreateWithFlags(&evF, cudaEventDisableTiming) == cudaSuccess);
        ok &= (cudaEventCreateWithFlags(&ev1, cudaEventDisableTiming) == cudaSuccess);
        ok &= (cudaEventCreateWithFlags(&ev2, cudaEventDisableTiming) == cudaSuccess);
        use_streams = ok;
    }

    // 0-2: serial prologue on origin stream
    pad_border_kernel<<<512, 256>>>(kpadp, vpadp);
    smooth_kernel<<<dim3(6, 6, BB*8), 256>>>(sup, csw, csb, smoothp);
    pw128_kernel<<<dim3(HW_/256, BB), 256>>>(sup, smoothp, crw, crb, sup2p, kpadp);

    if (use_streams) {
        // fork: per-level v-conv + natten chains in parallel
        cudaEventRecord(evF, 0);
        cudaStreamWaitEvent(t1, evF, 0);
        cudaStreamWaitEvent(t2, evF, 0);

        pw64_kernel<<<dim3(HW_/256, BB), 256, 0, t1>>>(sup2p, vw[0], vb[0], vpadp + 0*(BB*32*PLANE));
        natten_kernel<3><<<dim3(6, 12, BB), 256, natten_smem_bytes(3), t1>>>(
            key, kpadp, vpadp + 0*(BB*32*PLANE), rpb[0], aggp + 0*(BB*CHW_));
        cudaEventRecord(ev1, t1);

        pw64_kernel<<<dim3(HW_/256, BB), 256, 0, t2>>>(sup2p, vw[1], vb[1], vpadp + 1*(BB*32*PLANE));
        natten_kernel<5><<<dim3(6, 12, BB), 256, natten_smem_bytes(5), t2>>>(
            key, kpadp, vpadp + 1*(BB*32*PLANE), rpb[1], aggp + 1*(BB*CHW_));
        cudaEventRecord(ev2, t2);

        pw64_kernel<<<dim3(HW_/256, BB), 256>>>(sup2p, vw[2], vb[2], vpadp + 2*(BB*32*PLANE));
        natten_kernel<7><<<dim3(6, 12, BB), 256, natten_smem_bytes(7)>>>(
            key, kpadp, vpadp + 2*(BB*32*PLANE), rpb[2], aggp + 2*(BB*CHW_));

        cudaStreamWaitEvent(0, ev1, 0);
        cudaStreamWaitEvent(0, ev2, 0);
    } else {
        for (int l = 0; l < 3; l++)
            pw64_kernel<<<dim3(HW_/256, BB), 256>>>(sup2p, vw[l], vb[l], vpadp + l*(BB*32*PLANE));
        natten_kernel<3><<<dim3(6, 12, BB), 256, natten_smem_bytes(3)>>>(
            key, kpadp, vpadp + 0*(BB*32*PLANE), rpb[0], aggp + 0*(BB*CHW_));
        natten_kernel<5><<<dim3(6, 12, BB), 256, natten_smem_bytes(5)>>>(
            key, kpadp, vpadp + 1*(BB*32*PLANE), rpb[1], aggp + 1*(BB*CHW_));
        natten_kernel<7><<<dim3(6, 12, BB), 256, natten_smem_bytes(7)>>>(
            key, kpadp, vpadp + 2*(BB*32*PLANE), rpb[2], aggp + 2*(BB*CHW_));
    }

    // 4. fusion 3x3 + ReLU
    fusion_kernel<<<dim3(6, 6, BB), 512, (5760 + 20480)*4>>>(sup, aggp, fw, fb, out);
}